// round 15
// baseline (speedup 1.0000x reference)
#include <cuda_runtime.h>
#include <cstdint>

#define SH 68                    // smem row stride in floats
#define SZ (64 * SH)             // padded 64x64 matrix (floats)
#define NHEADS 8
#define NMAX 2048
#define MASK56 0x00FFFFFFFFFFFFFFull

// ---------------- device scratch ----------------
__device__ float g_powers[NHEADS][16][4096];     // g_powers[h][k] = B_h^k
__device__ float g_sos[4096];
__device__ int   g_key[NMAX];
__device__ int   g_perm[NMAX];

// dup a scalar into a packed f32x2 register (one MOV)
#define DUPF2(t, b)  asm("mov.b64 %0, {%1,%1};" : "=l"(t) : "f"(b))
// pure packed FFMA, no MOVs
#define FFMA2P(acc, a2, b2)                                                   \
    asm("fma.rn.f32x2 %0, %1, %2, %0;" : "+l"(acc) : "l"(a2), "l"(b2))

__device__ __forceinline__ float f2lo(unsigned long long v) {
    return __uint_as_float((unsigned)(v & 0xffffffffull));
}
__device__ __forceinline__ float f2hi(unsigned long long v) {
    return __uint_as_float((unsigned)(v >> 32));
}

// ---- 64x64 mm core (512 thr): result = (AT)^T * B.
// Lane tile 4 rows x 2 cols; per j: 1 LDS.128 + 1 LDS.64 + 2 MOV + 4 FFMA2.
__device__ __forceinline__ void mm_acc(const float* __restrict__ AT,
                                       const float* __restrict__ B,
                                       unsigned long long acc[4],
                                       int r0, int c0) {
    const float* ap = AT + r0;
    const float* bp = B + c0;
    acc[0] = acc[1] = acc[2] = acc[3] = 0ull;
#pragma unroll 8
    for (int j = 0; j < 64; j++) {
        ulonglong2 av = *(const ulonglong2*)(ap + j * SH);
        float2 bb = *(const float2*)(bp + j * SH);
        unsigned long long t0, t1;
        DUPF2(t0, bb.x);
        DUPF2(t1, bb.y);
        FFMA2P(acc[0], av.x, t0);
        FFMA2P(acc[1], av.x, t1);
        FFMA2P(acc[2], av.y, t0);
        FFMA2P(acc[3], av.y, t1);
    }
}

// ============ kernel A: prepare + steps + grouping, 146 blocks =============
// Grid fits in the first placement wave (<=148) so every block owns one SM:
//   b 0..79  : expm(k*H_h)  (h = b/10, k = b%10 + 1)   [deg-6 PS, 3 matmuls]
//   b 80     : expm(H_sos)
//   b 81..144: steps, 32 rows per block (hidden under prepare, own SMs)
//   b 145    : grouping (key + perm for maps)
__global__ void __launch_bounds__(512, 1)
kernelA(const float* __restrict__ raw, const int* __restrict__ pw, int L,
        float* __restrict__ steps_out, int has_steps) {
    extern __shared__ float sm[];
    int b = blockIdx.x;
    int tid = threadIdx.x;

    if (b >= 81 && b <= 144) {   // ---------------- steps ----------------
        if (has_steps) {
            unsigned long long* tbl = (unsigned long long*)sm;   // 2048 packs
#pragma unroll
            for (int q = 0; q < 4; q++) {
                int n = (tid << 2) + q;
                const int* p = pw + (size_t)n * L;
                unsigned long long pack = 0ull;
                int len = 0;
                for (int t = 0; t < L; t++) {
                    int wv = p[t];
                    int code = (wv == -1) ? 0 : wv;
                    pack |= ((unsigned long long)(code & 3)) << (2 * t);
                    if (wv != 3) len++;                  // PAD = 3
                }
                tbl[n] = pack | ((unsigned long long)len << 56);
            }
            __syncthreads();
            int i0 = (b - 81) << 5;                      // 32 rows per block
            int j0 = tid << 2;
            unsigned long long pj0 = tbl[j0], pj1 = tbl[j0 + 1];
            unsigned long long pj2 = tbl[j0 + 2], pj3 = tbl[j0 + 3];
#pragma unroll 4
            for (int rr = 0; rr < 32; rr++) {
                int i = i0 + rr;
                unsigned long long pi = tbl[i];
                int li = (int)(pi >> 56);
                unsigned long long pjs[4] = {pj0, pj1, pj2, pj3};
                float v[4];
#pragma unroll
                for (int q = 0; q < 4; q++) {
                    unsigned long long pj = pjs[q];
                    int lj = (int)(pj >> 56);
                    unsigned long long d = (pi ^ pj) & MASK56;
                    int pos = d ? ((__ffsll((long long)d) - 1) >> 1) : 64;
                    int mn = min(li, lj), mx = max(li, lj);
                    v[q] = (float)(mx - min(pos, mn));
                }
                __stcs((float4*)(steps_out + (size_t)i * NMAX + j0),
                       make_float4(v[0], v[1], v[2], v[3]));
            }
        }
        cudaTriggerProgrammaticLaunchCompletion();
        return;
    }

    if (b == 145) {   // ---------------- grouping ----------------
        int* cnt = (int*)sm;
        int* off = cnt + 32;
        if (tid < 20) cnt[tid] = 0;
        __syncthreads();
        for (int n = tid; n < NMAX; n += 512) {
            const int* p = pw + (size_t)n * L;
            int c = 0;
            for (int t = 0; t < L; t++) c += (p[t] == 1);
            int key = (p[0] == -1) ? 100 : c;
            g_key[n] = key;
            atomicAdd(&cnt[(key == 100) ? 16 : key], 1);
        }
        __syncthreads();
        if (tid == 0) { int s = 0; for (int q = 0; q < 20; q++) { off[q] = s; s += cnt[q]; } }
        __syncthreads();
        for (int n = tid; n < NMAX; n += 512) {
            int key = g_key[n];
            int pos = atomicAdd(&off[(key == 100) ? 16 : key], 1);
            g_perm[pos] = n;
        }
        cudaTriggerProgrammaticLaunchCompletion();
        return;
    }

    // ---------------- prepare: B_h^k = expm(k*H_h), deg-6 PS --------------
    int h, kk;
    const float* A;
    if (b == 80) { h = -1; kk = 1; A = raw + (size_t)16 * 4096; }
    else         { h = b / 10; kk = b % 10 + 1; A = raw + (size_t)(8 + h) * 4096; }

    float* M  = sm + 0 * SZ;
    float* P2 = sm + 1 * SZ;
    float* P3 = sm + 2 * SZ;
    float* W  = sm + 3 * SZ;    // A-stage, then B1' polynomial

    // 16 warps: warp tile 16 rows x 16 cols; lane tile 4 rows x 2 cols
    int w = tid >> 5, l = tid & 31;
    int r0 = (w >> 2) * 16 + (l >> 3) * 4;
    int c0 = (w & 3) * 16 + (l & 7) * 2;

    // Stage A into smem coalesced, then build M from smem.
    {
        int rr = tid >> 3;                 // 64 rows, 8 threads per row
        int cc0 = (tid & 7) << 3;
        float4 a0 = *(const float4*)(A + rr * 64 + cc0);
        float4 a1 = *(const float4*)(A + rr * 64 + cc0 + 4);
        *(float4*)(W + rr * SH + cc0)     = a0;
        *(float4*)(W + rr * SH + cc0 + 4) = a1;
    }
    __syncthreads();
    float scale = (float)kk * (1.0f / 64.0f);
    for (int i = tid; i < 4096; i += 512) {
        int rr = i >> 6, cc = i & 63;
        M[rr * SH + cc] = (W[rr * SH + cc] - W[cc * SH + rr]) * scale;
    }
    __syncthreads();

    unsigned long long acc[4];

    // P2 = M*M = -(Mt*M)
    mm_acc(M, M, acc, r0, c0);
#pragma unroll
    for (int p = 0; p < 2; p++)
#pragma unroll
        for (int i = 0; i < 2; i++) {
            int r = r0 + 2 * p + i;
            float vx = i ? -f2hi(acc[2 * p])     : -f2lo(acc[2 * p]);
            float vy = i ? -f2hi(acc[2 * p + 1]) : -f2lo(acc[2 * p + 1]);
            *(float2*)(P2 + r * SH + c0) = make_float2(vx, vy);
        }
    __syncthreads();

    // P3 = M*P2 = -(Mt*P2); fused W = B1' = M/24 + P2/120 + P3/720
    mm_acc(M, P2, acc, r0, c0);
    __syncthreads();                       // A-staging reads of W fully drained
#pragma unroll
    for (int p = 0; p < 2; p++)
#pragma unroll
        for (int i = 0; i < 2; i++) {
            int r = r0 + 2 * p + i;
            float p3x = i ? -f2hi(acc[2 * p])     : -f2lo(acc[2 * p]);
            float p3y = i ? -f2hi(acc[2 * p + 1]) : -f2lo(acc[2 * p + 1]);
            *(float2*)(P3 + r * SH + c0) = make_float2(p3x, p3y);
            float2 mv  = *(const float2*)(M  + r * SH + c0);
            float2 p2v = *(const float2*)(P2 + r * SH + c0);
            float2 wv;
            wv.x = (1.f / 24.f) * mv.x + (1.f / 120.f) * p2v.x + (1.f / 720.f) * p3x;
            wv.y = (1.f / 24.f) * mv.y + (1.f / 120.f) * p2v.y + (1.f / 720.f) * p3y;
            *(float2*)(W + r * SH + c0) = wv;
        }
    __syncthreads();

    // E = B0' + P3*W = B0' - (P3t*W);  B0' = I + M + P2/2 + P3/6
    mm_acc(P3, W, acc, r0, c0);
    float* dst = (h < 0) ? g_sos : g_powers[h][kk];
#pragma unroll
    for (int p = 0; p < 2; p++)
#pragma unroll
        for (int i = 0; i < 2; i++) {
            int r = r0 + 2 * p + i;
            float px = i ? f2hi(acc[2 * p])     : f2lo(acc[2 * p]);
            float py = i ? f2hi(acc[2 * p + 1]) : f2lo(acc[2 * p + 1]);
            float2 mv  = *(const float2*)(M  + r * SH + c0);
            float2 p2v = *(const float2*)(P2 + r * SH + c0);
            float2 p3v = *(const float2*)(P3 + r * SH + c0);
            float d0 = (r == c0)     ? 1.f : 0.f;
            float d1 = (r == c0 + 1) ? 1.f : 0.f;
            float ex = d0 + mv.x + 0.5f * p2v.x + (1.f / 6.f) * p3v.x - px;
            float ey = d1 + mv.y + 0.5f * p2v.y + (1.f / 6.f) * p3v.y - py;
            *(float2*)(dst + r * 64 + c0) = make_float2(ex, ey);
            if (h >= 0 && kk == 1)    // publish identity as power 0 once per head
                *(float2*)(g_powers[h][0] + r * 64 + c0) = make_float2(d0, d1);
        }
    cudaTriggerProgrammaticLaunchCompletion();
}

// =================== kernel B: maps gather-broadcast (256 MB) ==============
__global__ void __launch_bounds__(256)
maps_writer(float4* __restrict__ out) {
    cudaGridDependencySynchronize();       // PDL: wait for kernelA's writes
    int b = blockIdx.x;
    int h = b & 7;
    int base = (b >> 3) << 3;
    int t = threadIdx.x;
    float4 v0, v1, v2, v3;
    int cached = -12345;
#pragma unroll 1
    for (int e = 0; e < 8; e++) {
        int n = g_perm[base + e];
        int key = g_key[n];
        if (key != cached) {
            const float4* src = (key == 100) ? (const float4*)g_sos
                                             : (const float4*)g_powers[h][key];
            v0 = src[t]; v1 = src[t + 256]; v2 = src[t + 512]; v3 = src[t + 768];
            cached = key;
        }
        float4* dst = out + ((size_t)((unsigned)(n * NHEADS + h)) << 10);
        __stcs(dst + t,       v0);
        __stcs(dst + t + 256, v1);
        __stcs(dst + t + 512, v2);
        __stcs(dst + t + 768, v3);
    }
}

// ---------------- launch --------------------------------------------------
extern "C" void kernel_launch(void* const* d_in, const int* in_sizes, int n_in,
                              void* d_out, int out_size) {
    const float* raw = (const float*)d_in[0];
    const int*   pw  = (const int*)d_in[1];
    const int L = in_sizes[1] / NMAX;
    float* out = (float*)d_out;

    size_t maps_elems = (size_t)NMAX * NHEADS * 4096;
    int has_steps = ((size_t)out_size >= maps_elems + (size_t)NMAX * NMAX) ? 1 : 0;

    size_t smem = 4ull * SZ * sizeof(float);   // 69632 B (4 slots)
    cudaFuncSetAttribute(kernelA, cudaFuncAttributeMaxDynamicSharedMemorySize,
                         (int)smem);

    kernelA<<<146, 512, smem>>>(raw, pw, L, out + maps_elems, has_steps);

    // PDL launch: maps_writer may be scheduled while kernelA drains; it gates
    // itself with cudaGridDependencySynchronize().
    cudaLaunchConfig_t cfg = {};
    cfg.gridDim = dim3(2048);
    cfg.blockDim = dim3(256);
    cfg.dynamicSmemBytes = 0;
    cfg.stream = 0;
    cudaLaunchAttribute attrs[1];
    attrs[0].id = cudaLaunchAttributeProgrammaticStreamSerialization;
    attrs[0].val.programmaticStreamSerializationAllowed = 1;
    cfg.attrs = attrs;
    cfg.numAttrs = 1;
    cudaLaunchKernelEx(&cfg, maps_writer, (float4*)out);
}

// round 16
// speedup vs baseline: 1.0118x; 1.0118x over previous
#include <cuda_runtime.h>
#include <cstdint>

#define SH 68                    // smem row stride in floats
#define SZ (64 * SH)             // padded 64x64 matrix (floats)
#define NHEADS 8
#define NMAX 2048
#define MASK56 0x00FFFFFFFFFFFFFFull

// ---------------- device scratch ----------------
__device__ float g_powers[NHEADS][16][4096];     // g_powers[h][k] = B_h^k
__device__ float g_sos[4096];
__device__ int   g_key[NMAX];
__device__ int   g_perm[NMAX];

// dup a scalar into a packed f32x2 register (one MOV)
#define DUPF2(t, b)  asm("mov.b64 %0, {%1,%1};" : "=l"(t) : "f"(b))
// pure packed FFMA, no MOVs
#define FFMA2P(acc, a2, b2)                                                   \
    asm("fma.rn.f32x2 %0, %1, %2, %0;" : "+l"(acc) : "l"(a2), "l"(b2))

__device__ __forceinline__ float f2lo(unsigned long long v) {
    return __uint_as_float((unsigned)(v & 0xffffffffull));
}
__device__ __forceinline__ float f2hi(unsigned long long v) {
    return __uint_as_float((unsigned)(v >> 32));
}

// ---- 64x64 mm core (512 thr): result = (AT)^T * B.
// Lane tile 4 rows x 2 cols; per j: 1 LDS.128 + 1 LDS.64 + 2 MOV + 4 FFMA2.
__device__ __forceinline__ void mm_acc(const float* __restrict__ AT,
                                       const float* __restrict__ B,
                                       unsigned long long acc[4],
                                       int r0, int c0) {
    const float* ap = AT + r0;
    const float* bp = B + c0;
    acc[0] = acc[1] = acc[2] = acc[3] = 0ull;
#pragma unroll 8
    for (int j = 0; j < 64; j++) {
        ulonglong2 av = *(const ulonglong2*)(ap + j * SH);
        float2 bb = *(const float2*)(bp + j * SH);
        unsigned long long t0, t1;
        DUPF2(t0, bb.x);
        DUPF2(t1, bb.y);
        FFMA2P(acc[0], av.x, t0);
        FFMA2P(acc[1], av.x, t1);
        FFMA2P(acc[2], av.y, t0);
        FFMA2P(acc[3], av.y, t1);
    }
}

// ============ kernel A: prepare + steps + grouping, 146 blocks =============
// Grid fits in the first placement wave (<=148) so every block owns one SM:
//   b 0..79  : expm(k*H_h)  (h = b/10, k = b%10 + 1)   [deg-6 PS, 3 matmuls]
//   b 80     : expm(H_sos)
//   b 81..144: steps, 32 rows per block (coalesced pw staging via smem)
//   b 145    : grouping (key + perm for maps)
__global__ void __launch_bounds__(512, 1)
kernelA(const float* __restrict__ raw, const int* __restrict__ pw, int L,
        float* __restrict__ steps_out, int has_steps) {
    extern __shared__ float sm[];
    int b = blockIdx.x;
    int tid = threadIdx.x;

    if (b >= 81 && b <= 144) {   // ---------------- steps ----------------
        if (has_steps) {
            // Stage pw coalesced into smem (stride-512 LDG.32 = 1 line/warp),
            // THEN pack from smem. Avoids the 32-line-per-LDG gather pattern.
            int* ipw = (int*)sm;                                   // 2048*L ints
            unsigned long long* tbl =
                (unsigned long long*)(sm + (size_t)L * NMAX);      // 16 KB table
            int total = L * NMAX;
            for (int i = tid; i < total; i += 512) ipw[i] = pw[i];
            __syncthreads();
#pragma unroll
            for (int q = 0; q < 4; q++) {
                int n = (tid << 2) + q;
                const int* p = ipw + n * L;
                unsigned long long pack = 0ull;
                int len = 0;
                for (int t = 0; t < L; t++) {
                    int wv = p[t];
                    int code = (wv == -1) ? 0 : wv;
                    pack |= ((unsigned long long)(code & 3)) << (2 * t);
                    if (wv != 3) len++;                  // PAD = 3
                }
                tbl[n] = pack | ((unsigned long long)len << 56);
            }
            __syncthreads();
            int i0 = (b - 81) << 5;                      // 32 rows per block
            int j0 = tid << 2;
            unsigned long long pj0 = tbl[j0], pj1 = tbl[j0 + 1];
            unsigned long long pj2 = tbl[j0 + 2], pj3 = tbl[j0 + 3];
#pragma unroll 4
            for (int rr = 0; rr < 32; rr++) {
                int i = i0 + rr;
                unsigned long long pi = tbl[i];
                int li = (int)(pi >> 56);
                unsigned long long pjs[4] = {pj0, pj1, pj2, pj3};
                float v[4];
#pragma unroll
                for (int q = 0; q < 4; q++) {
                    unsigned long long pj = pjs[q];
                    int lj = (int)(pj >> 56);
                    unsigned long long d = (pi ^ pj) & MASK56;
                    int pos = d ? ((__ffsll((long long)d) - 1) >> 1) : 64;
                    int mn = min(li, lj), mx = max(li, lj);
                    v[q] = (float)(mx - min(pos, mn));
                }
                __stcs((float4*)(steps_out + (size_t)i * NMAX + j0),
                       make_float4(v[0], v[1], v[2], v[3]));
            }
        }
        cudaTriggerProgrammaticLaunchCompletion();
        return;
    }

    if (b == 145) {   // ---------------- grouping ----------------
        // Same coalesced staging trick as steps.
        int* ipw = (int*)(sm + 64);
        int* cnt = (int*)sm;
        int* off = cnt + 32;
        int total = L * NMAX;
        for (int i = tid; i < total; i += 512) ipw[i] = pw[i];
        if (tid < 20) cnt[tid] = 0;
        __syncthreads();
        for (int n = tid; n < NMAX; n += 512) {
            const int* p = ipw + n * L;
            int c = 0;
            for (int t = 0; t < L; t++) c += (p[t] == 1);
            int key = (p[0] == -1) ? 100 : c;
            g_key[n] = key;
            atomicAdd(&cnt[(key == 100) ? 16 : key], 1);
        }
        __syncthreads();
        if (tid == 0) { int s = 0; for (int q = 0; q < 20; q++) { off[q] = s; s += cnt[q]; } }
        __syncthreads();
        for (int n = tid; n < NMAX; n += 512) {
            int key = g_key[n];
            int pos = atomicAdd(&off[(key == 100) ? 16 : key], 1);
            g_perm[pos] = n;
        }
        cudaTriggerProgrammaticLaunchCompletion();
        return;
    }

    // ---------------- prepare: B_h^k = expm(k*H_h), deg-6 PS --------------
    int h, kk;
    const float* A;
    if (b == 80) { h = -1; kk = 1; A = raw + (size_t)16 * 4096; }
    else         { h = b / 10; kk = b % 10 + 1; A = raw + (size_t)(8 + h) * 4096; }

    float* M  = sm + 0 * SZ;
    float* P2 = sm + 1 * SZ;
    float* P3 = sm + 2 * SZ;
    float* W  = sm + 3 * SZ;    // A-stage, then B1' polynomial

    // 16 warps: warp tile 16 rows x 16 cols; lane tile 4 rows x 2 cols
    int w = tid >> 5, l = tid & 31;
    int r0 = (w >> 2) * 16 + (l >> 3) * 4;
    int c0 = (w & 3) * 16 + (l & 7) * 2;

    // Stage A into smem coalesced, then build M from smem.
    {
        int rr = tid >> 3;                 // 64 rows, 8 threads per row
        int cc0 = (tid & 7) << 3;
        float4 a0 = *(const float4*)(A + rr * 64 + cc0);
        float4 a1 = *(const float4*)(A + rr * 64 + cc0 + 4);
        *(float4*)(W + rr * SH + cc0)     = a0;
        *(float4*)(W + rr * SH + cc0 + 4) = a1;
    }
    __syncthreads();
    float scale = (float)kk * (1.0f / 64.0f);
    for (int i = tid; i < 4096; i += 512) {
        int rr = i >> 6, cc = i & 63;
        M[rr * SH + cc] = (W[rr * SH + cc] - W[cc * SH + rr]) * scale;
    }
    __syncthreads();

    unsigned long long acc[4];

    // P2 = M*M = -(Mt*M)
    mm_acc(M, M, acc, r0, c0);
#pragma unroll
    for (int p = 0; p < 2; p++)
#pragma unroll
        for (int i = 0; i < 2; i++) {
            int r = r0 + 2 * p + i;
            float vx = i ? -f2hi(acc[2 * p])     : -f2lo(acc[2 * p]);
            float vy = i ? -f2hi(acc[2 * p + 1]) : -f2lo(acc[2 * p + 1]);
            *(float2*)(P2 + r * SH + c0) = make_float2(vx, vy);
        }
    __syncthreads();

    // P3 = M*P2 = -(Mt*P2); fused W = B1' = M/24 + P2/120 + P3/720
    mm_acc(M, P2, acc, r0, c0);
    __syncthreads();                       // A-staging reads of W fully drained
#pragma unroll
    for (int p = 0; p < 2; p++)
#pragma unroll
        for (int i = 0; i < 2; i++) {
            int r = r0 + 2 * p + i;
            float p3x = i ? -f2hi(acc[2 * p])     : -f2lo(acc[2 * p]);
            float p3y = i ? -f2hi(acc[2 * p + 1]) : -f2lo(acc[2 * p + 1]);
            *(float2*)(P3 + r * SH + c0) = make_float2(p3x, p3y);
            float2 mv  = *(const float2*)(M  + r * SH + c0);
            float2 p2v = *(const float2*)(P2 + r * SH + c0);
            float2 wv;
            wv.x = (1.f / 24.f) * mv.x + (1.f / 120.f) * p2v.x + (1.f / 720.f) * p3x;
            wv.y = (1.f / 24.f) * mv.y + (1.f / 120.f) * p2v.y + (1.f / 720.f) * p3y;
            *(float2*)(W + r * SH + c0) = wv;
        }
    __syncthreads();

    // E = B0' + P3*W = B0' - (P3t*W);  B0' = I + M + P2/2 + P3/6
    mm_acc(P3, W, acc, r0, c0);
    float* dst = (h < 0) ? g_sos : g_powers[h][kk];
#pragma unroll
    for (int p = 0; p < 2; p++)
#pragma unroll
        for (int i = 0; i < 2; i++) {
            int r = r0 + 2 * p + i;
            float px = i ? f2hi(acc[2 * p])     : f2lo(acc[2 * p]);
            float py = i ? f2hi(acc[2 * p + 1]) : f2lo(acc[2 * p + 1]);
            float2 mv  = *(const float2*)(M  + r * SH + c0);
            float2 p2v = *(const float2*)(P2 + r * SH + c0);
            float2 p3v = *(const float2*)(P3 + r * SH + c0);
            float d0 = (r == c0)     ? 1.f : 0.f;
            float d1 = (r == c0 + 1) ? 1.f : 0.f;
            float ex = d0 + mv.x + 0.5f * p2v.x + (1.f / 6.f) * p3v.x - px;
            float ey = d1 + mv.y + 0.5f * p2v.y + (1.f / 6.f) * p3v.y - py;
            *(float2*)(dst + r * 64 + c0) = make_float2(ex, ey);
            if (h >= 0 && kk == 1)    // publish identity as power 0 once per head
                *(float2*)(g_powers[h][0] + r * 64 + c0) = make_float2(d0, d1);
        }
    cudaTriggerProgrammaticLaunchCompletion();
}

// =================== kernel B: maps gather-broadcast (256 MB) ==============
__global__ void __launch_bounds__(256)
maps_writer(float4* __restrict__ out) {
    cudaGridDependencySynchronize();       // PDL: wait for kernelA's writes
    int b = blockIdx.x;
    int h = b & 7;
    int base = (b >> 3) << 3;
    int t = threadIdx.x;
    float4 v0, v1, v2, v3;
    int cached = -12345;
#pragma unroll 1
    for (int e = 0; e < 8; e++) {
        int n = g_perm[base + e];
        int key = g_key[n];
        if (key != cached) {
            const float4* src = (key == 100) ? (const float4*)g_sos
                                             : (const float4*)g_powers[h][key];
            v0 = src[t]; v1 = src[t + 256]; v2 = src[t + 512]; v3 = src[t + 768];
            cached = key;
        }
        float4* dst = out + ((size_t)((unsigned)(n * NHEADS + h)) << 10);
        __stcs(dst + t,       v0);
        __stcs(dst + t + 256, v1);
        __stcs(dst + t + 512, v2);
        __stcs(dst + t + 768, v3);
    }
}

// ---------------- launch --------------------------------------------------
extern "C" void kernel_launch(void* const* d_in, const int* in_sizes, int n_in,
                              void* d_out, int out_size) {
    const float* raw = (const float*)d_in[0];
    const int*   pw  = (const int*)d_in[1];
    const int L = in_sizes[1] / NMAX;
    float* out = (float*)d_out;

    size_t maps_elems = (size_t)NMAX * NHEADS * 4096;
    int has_steps = ((size_t)out_size >= maps_elems + (size_t)NMAX * NMAX) ? 1 : 0;

    size_t prep_smem  = 4ull * SZ * sizeof(float);                 // 69632 B
    size_t steps_smem = (size_t)L * NMAX * sizeof(int) + 16384 + 256;
    size_t smem = prep_smem > steps_smem ? prep_smem : steps_smem;
    cudaFuncSetAttribute(kernelA, cudaFuncAttributeMaxDynamicSharedMemorySize,
                         (int)smem);

    kernelA<<<146, 512, smem>>>(raw, pw, L, out + maps_elems, has_steps);

    // PDL launch: maps_writer may be scheduled while kernelA drains; it gates
    // itself with cudaGridDependencySynchronize().
    cudaLaunchConfig_t cfg = {};
    cfg.gridDim = dim3(2048);
    cfg.blockDim = dim3(256);
    cfg.dynamicSmemBytes = 0;
    cfg.stream = 0;
    cudaLaunchAttribute attrs[1];
    attrs[0].id = cudaLaunchAttributeProgrammaticStreamSerialization;
    attrs[0].val.programmaticStreamSerializationAllowed = 1;
    cfg.attrs = attrs;
    cfg.numAttrs = 1;
    cudaLaunchKernelEx(&cfg, maps_writer, (float4*)out);
}